// round 15
// baseline (speedup 1.0000x reference)
#include <cuda_runtime.h>
#include <cuda_fp16.h>
#include <cstdint>

#define N_NODES 50000
#define N_EDGES 800000
#define TILE_M  256
#define NTILES  (N_EDGES / TILE_M)   // 3125
#define THREADS 256

// ---- smem layout (bytes) ----
#define OFF_BP   0                               // 64nt * 2kpair * 32lane * 16B = 64K
#define OFF_ZS   65536                           // 2 bufs * 256 rows * 80B (z[16] + at[4])
#define OFF_EM   (OFF_ZS + 2*256*80)             // 2 bufs * 256 rows * 80B (emb 64B + pad)
#define OFF_VJ   (OFF_EM + 2*256*80)             // 2 bufs * 256 int
#define SMEM_TOTAL (OFF_VJ + 2*256*4)            // 149504 B

__device__ float g_esum[N_NODES * 8];
__device__ unsigned int g_bar = 0;   // monotonic ticket counter (never reset; round-up target)

// pack two f32 -> f16x2 (first arg -> low half)
__device__ __forceinline__ uint32_t pack_f16x2(float lo, float hi) {
    uint32_t r;
    asm("cvt.rn.f16x2.f32 %0, %1, %2;" : "=r"(r) : "f"(hi), "f"(lo));
    return r;
}

__device__ __forceinline__ uint32_t smem_u32(const void* p) {
    uint32_t a;
    asm("{ .reg .u64 t; cvta.to.shared.u64 t, %1; cvt.u32.u64 %0, t; }"
        : "=r"(a) : "l"(p));
    return a;
}

__device__ __forceinline__ void cp16(uint32_t dst, const void* src) {
    asm volatile("cp.async.cg.shared.global [%0], [%1], 16;"
                 :: "r"(dst), "l"(src) : "memory");
}
#define CP_COMMIT() asm volatile("cp.async.commit_group;" ::: "memory")
#define CP_WAIT0()  asm volatile("cp.async.wait_group 0;" ::: "memory")

__device__ __forceinline__ void mma_f16(float d[4],
                                        uint32_t a0, uint32_t a1, uint32_t a2, uint32_t a3,
                                        uint32_t b0, uint32_t b1) {
    asm volatile(
        "mma.sync.aligned.m16n8k16.row.col.f32.f16.f16.f32 "
        "{%0,%1,%2,%3}, {%4,%5,%6,%7}, {%8,%9}, {%0,%1,%2,%3};"
        : "+f"(d[0]), "+f"(d[1]), "+f"(d[2]), "+f"(d[3])
        : "r"(a0), "r"(a1), "r"(a2), "r"(a3), "r"(b0), "r"(b1));
}

// C = 0 variant (no accumulator zeroing MOVs)
__device__ __forceinline__ void mma_f16_z(float d[4],
                                          uint32_t a0, uint32_t a1, uint32_t a2, uint32_t a3,
                                          uint32_t b0, uint32_t b1, float zz) {
    asm volatile(
        "mma.sync.aligned.m16n8k16.row.col.f32.f16.f16.f32 "
        "{%0,%1,%2,%3}, {%4,%5,%6,%7}, {%8,%9}, {%10,%10,%10,%10};"
        : "=f"(d[0]), "=f"(d[1]), "=f"(d[2]), "=f"(d[3])
        : "r"(a0), "r"(a1), "r"(a2), "r"(a3), "r"(b0), "r"(b1), "f"(zz));
}

__device__ __forceinline__ float fsilu(float s) {
    return __fdividef(s, 1.0f + __expf(-s));
}

__device__ __forceinline__ void red_addf(float* p, float v) {
    asm volatile("red.global.add.f32 [%0], %1;" :: "l"(p), "f"(v) : "memory");
}

// grid-wide spin barrier on a monotonic ticket counter.
// Each call consumes gridDim.x tickets; target = next multiple of gridDim.x.
// Correct across CUDA-graph replays (counter never reset).
__device__ __forceinline__ void grid_barrier(int tid) {
    __threadfence();                    // release prior writes (incl. RED)
    if (tid == 0) {
        const unsigned g = gridDim.x;
        unsigned t = atomicAdd(&g_bar, 1u) + 1u;
        unsigned target = ((t + g - 1u) / g) * g;
        while (atomicAdd(&g_bar, 0u) < target) { }
    }
    __syncthreads();
    __threadfence();                    // acquire side
}

__global__ __launch_bounds__(THREADS, 1)
void edge_kernel(const float* __restrict__ x,
                 const int*   __restrict__ ei,
                 const float* __restrict__ attr,
                 const float* __restrict__ emb,
                 const float* __restrict__ w1,
                 const float* __restrict__ w2,
                 const float* __restrict__ w_node,
                 float*       __restrict__ edge_out,
                 float*       __restrict__ x_out)
{
    extern __shared__ char smem[];
    const uint32_t sb = smem_u32(smem);
    const int tid  = threadIdx.x;
    const int lane = tid & 31;
    const int gID  = lane >> 2;
    const int tig  = lane & 3;
    const int wid  = tid >> 5;

    // ---- fused zero of g_esum (grid-stride slice per CTA) ----
    {
        float4* ez = (float4*)g_esum;
        const int tot = N_NODES * 2;          // float4 count
        for (int i = blockIdx.x * THREADS + tid; i < tot; i += gridDim.x * THREADS)
            ez[i] = make_float4(0.f, 0.f, 0.f, 0.f);
    }

    // ---- w1 B-fragments in registers, fp16 hi/lo split (persist whole kernel)
    uint32_t w1h[8][2], w1l[8][2];
    #pragma unroll
    for (int nt = 0; nt < 8; nt++) {
        const int c = nt * 8 + gID;
        #pragma unroll
        for (int jj = 0; jj < 2; jj++) {
            const int d0 = 2 * tig + jj * 8;
            float v0 = w1[d0 * 64 + c];
            float v1 = w1[(d0 + 1) * 64 + c];
            float h0 = __half2float(__float2half_rn(v0));
            float h1 = __half2float(__float2half_rn(v1));
            w1h[nt][jj] = pack_f16x2(h0, h1);
            w1l[nt][jj] = pack_f16x2(v0 - h0, v1 - h1);
        }
    }

    // ---- preload W2 as packed single-fp16 B fragments ----
    for (int ent = tid; ent < 4096; ent += THREADS) {
        int l  = ent & 31;
        int kp = (ent >> 5) & 1;
        int nt = ent >> 6;
        int n  = nt * 8 + (l >> 2);
        uint4 pk;
        #pragma unroll
        for (int half = 0; half < 2; half++) {
            int ks = kp * 2 + half;
            int k0 = ks * 16 + (l & 3) * 2;
            float v0 = w2[(k0    ) * 512 + n];
            float v1 = w2[(k0 + 1) * 512 + n];
            float v2 = w2[(k0 + 8) * 512 + n];
            float v3 = w2[(k0 + 9) * 512 + n];
            if (half == 0) { pk.x = pack_f16x2(v0, v1); pk.y = pack_f16x2(v2, v3); }
            else           { pk.z = pack_f16x2(v0, v1); pk.w = pack_f16x2(v2, v3); }
        }
        *(uint4*)(smem + OFF_BP + (size_t)ent * 16) = pk;
    }

    // ---- prologue: stage tile0 into buf 0 (direct) ----
    {
        const int e = blockIdx.x * TILE_M + tid;
        const int vi = ei[e];
        const int vj = ei[N_EDGES + e];
        float4* zr = (float4*)(smem + OFF_ZS + (size_t)tid * 80);
        const float4* xp = (const float4*)(x + (size_t)vi * 8);
        zr[0] = xp[0]; zr[1] = xp[1];
        const float4* xq = (const float4*)(x + (size_t)vj * 8);
        zr[2] = xq[0]; zr[3] = xq[1];
        zr[4] = ((const float4*)attr)[e];
        float4* er = (float4*)(smem + OFF_EM + (size_t)tid * 80);
        const float4* ep = (const float4*)(emb + (size_t)e * 16);
        er[0] = ep[0]; er[1] = ep[1]; er[2] = ep[2]; er[3] = ep[3];
        *(int*)(smem + OFF_VJ + (size_t)tid * 4) = vj;
    }
    // ---- prefetch tile1's indices into registers (2 regs only) ----
    int nvi = 0, nvj = 0;
    {
        const int t1 = blockIdx.x + gridDim.x;
        if (t1 < NTILES) {
            const int e = t1 * TILE_M + tid;
            nvi = ei[e];
            nvj = ei[N_EDGES + e];
        }
    }

    // ---- barrier 1: zero slices visible before any RED ----
    grid_barrier(tid);

    int it = 0;
    for (int tile = blockIdx.x; tile < NTILES; tile += gridDim.x, it++) {
        const int buf  = it & 1;
        const int nbuf = buf ^ 1;
        const int ntile = tile + gridDim.x;
        const bool hn = (ntile < NTILES);

        // ---- issue async staging for tile+1 (no register residency) ----
        if (hn) {
            const int e1 = ntile * TILE_M + tid;
            const uint32_t zdst = sb + OFF_ZS + (uint32_t)(nbuf * 256 + tid) * 80;
            const float* xi = x + (size_t)nvi * 8;
            const float* xj = x + (size_t)nvj * 8;
            cp16(zdst,      xi);     cp16(zdst + 16, xi + 4);
            cp16(zdst + 32, xj);     cp16(zdst + 48, xj + 4);
            cp16(zdst + 64, attr + (size_t)e1 * 4);
            const uint32_t edst = sb + OFF_EM + (uint32_t)(nbuf * 256 + tid) * 80;
            const float* ep = emb + (size_t)e1 * 16;
            cp16(edst,      ep);     cp16(edst + 16, ep + 4);
            cp16(edst + 32, ep + 8); cp16(edst + 48, ep + 12);
            *(int*)(smem + OFF_VJ + (size_t)(nbuf * 256 + tid) * 4) = nvj;
            CP_COMMIT();
            // prefetch tile+2 indices
            const int nnt = ntile + gridDim.x;
            if (nnt < NTILES) {
                const int e2 = nnt * TILE_M + tid;
                nvi = ei[e2];
                nvj = ei[N_EDGES + e2];
            }
        }

        const int wbase = wid * 32;           // 8 warps x 32 edge-rows
        const float fz = 0.0f;
        #pragma unroll 1                      // keep contexts disjoint (R12 lesson)
        for (int mt = 0; mt < 2; mt++) {
            const int r0 = wbase + mt * 16 + gID;
            const int r8 = r0 + 8;
            const int e0 = tile * TILE_M + r0;
            const int e8 = tile * TILE_M + r8;

            // ---- emb A-fragments from staged smem, single fp16 ----
            uint32_t a16[4];
            {
                const char* er0 = smem + OFF_EM + (size_t)(buf * 256 + r0) * 80;
                const char* er8 = smem + OFF_EM + (size_t)(buf * 256 + r8) * 80;
                float2 v[4];
                v[0] = *(const float2*)(er0 + tig * 8);
                v[1] = *(const float2*)(er8 + tig * 8);
                v[2] = *(const float2*)(er0 + tig * 8 + 32);
                v[3] = *(const float2*)(er8 + tig * 8 + 32);
                #pragma unroll
                for (int q = 0; q < 4; q++)
                    a16[q] = pack_f16x2(v[q].x, v[q].y);
            }

            // ---- phase-1 MMA (2-pass: emb16 x (w1h + w1l)) -> silu -> A-frags
            uint32_t af[4][4];
            #pragma unroll
            for (int ks = 0; ks < 4; ks++) {
                #pragma unroll
                for (int j = 0; j < 2; j++) {
                    const int nt = 2 * ks + j;
                    float dd[4];
                    mma_f16_z(dd, a16[0], a16[1], a16[2], a16[3], w1h[nt][0], w1h[nt][1], fz);
                    mma_f16 (dd, a16[0], a16[1], a16[2], a16[3], w1l[nt][0], w1l[nt][1]);
                    float h0 = fsilu(dd[0] * 0.25f);
                    float h1 = fsilu(dd[1] * 0.25f);
                    float h2 = fsilu(dd[2] * 0.25f);
                    float h3 = fsilu(dd[3] * 0.25f);
                    af[ks][2 * j]     = pack_f16x2(h0, h1);   // (r0, k-cols)
                    af[ks][2 * j + 1] = pack_f16x2(h2, h3);   // (r8, k-cols)
                }
            }

            // ---- z / attr from staged smem (80B stride) ----
            float z0[16], z1[16], at0[4], at1[4];
            {
                const float4* q0 = (const float4*)(smem + OFF_ZS + (size_t)(buf * 256 + r0) * 80);
                const float4* q1 = (const float4*)(smem + OFF_ZS + (size_t)(buf * 256 + r8) * 80);
                #pragma unroll
                for (int q = 0; q < 4; q++) {
                    float4 a = q0[q]; z0[4*q]=a.x; z0[4*q+1]=a.y; z0[4*q+2]=a.z; z0[4*q+3]=a.w;
                    float4 b = q1[q]; z1[4*q]=b.x; z1[4*q+1]=b.y; z1[4*q+2]=b.z; z1[4*q+3]=b.w;
                }
                float4 a = q0[4]; at0[0]=a.x; at0[1]=a.y; at0[2]=a.z; at0[3]=a.w;
                float4 b = q1[4]; at1[0]=b.x; at1[1]=b.y; at1[2]=b.z; at1[3]=b.w;
            }

            float acc0 = 0.f, acc1 = 0.f, acc2 = 0.f, acc3 = 0.f;

            #pragma unroll
            for (int nt = 0; nt < 64; nt++) {      // FULL unroll: const z/at indices
                float d1[4];
                const uint4* bp = (const uint4*)(smem + OFF_BP + (size_t)nt * 1024) + lane;
                {
                    uint4 b01 = bp[0];        // ks0 (x,y), ks1 (z,w)
                    mma_f16_z(d1, af[0][0], af[0][1], af[0][2], af[0][3], b01.x, b01.y, fz);
                    mma_f16 (d1, af[1][0], af[1][1], af[1][2], af[1][3], b01.z, b01.w);
                }
                {
                    uint4 b23 = bp[32];       // ks2 (x,y), ks3 (z,w)
                    mma_f16 (d1, af[2][0], af[2][1], af[2][2], af[2][3], b23.x, b23.y);
                    mma_f16 (d1, af[3][0], af[3][1], af[3][2], af[3][3], b23.z, b23.w);
                }
                const float c0 = at0[nt >> 4] * z0[nt & 15];
                const float c1 = at1[nt >> 4] * z1[nt & 15];
                acc0 += c0 * d1[0];
                acc1 += c0 * d1[1];
                acc2 += c1 * d1[2];
                acc3 += c1 * d1[3];
            }

            const float sc = 1.0f / 64.0f;
            acc0 *= sc; acc1 *= sc; acc2 *= sc; acc3 *= sc;
            *(float2*)(edge_out + (size_t)e0 * 8 + 2 * tig) = make_float2(acc0, acc1);
            *(float2*)(edge_out + (size_t)e8 * 8 + 2 * tig) = make_float2(acc2, acc3);
            const int vj0 = *(const int*)(smem + OFF_VJ + (size_t)(buf * 256 + r0) * 4);
            const int vj1 = *(const int*)(smem + OFF_VJ + (size_t)(buf * 256 + r8) * 4);
            red_addf(g_esum + (size_t)vj0 * 8 + 2 * tig,     acc0);
            red_addf(g_esum + (size_t)vj0 * 8 + 2 * tig + 1, acc1);
            red_addf(g_esum + (size_t)vj1 * 8 + 2 * tig,     acc2);
            red_addf(g_esum + (size_t)vj1 * 8 + 2 * tig + 1, acc3);
        }

        CP_WAIT0();        // async staging for tile+1 has landed
        __syncthreads();
    }

    // ================= fused node phase =================
    // barrier 2: all REDs to g_esum are visible
    grid_barrier(tid);

    // w_node -> smem (staging regions are free now; syncthreads in barrier done)
    float* swn = (float*)(smem + OFF_ZS);
    for (int idx = tid; idx < 1024; idx += THREADS)
        swn[idx] = w_node[idx];
    __syncthreads();

    const float4* w4 = (const float4*)swn;
    for (int n = blockIdx.x * THREADS + tid; n < N_NODES; n += gridDim.x * THREADS) {
        float xv[8], ev[8];
        {
            const float4* xp = (const float4*)(x + (size_t)n * 8);
            float4 t0 = xp[0], t1 = xp[1];
            xv[0]=t0.x; xv[1]=t0.y; xv[2]=t0.z; xv[3]=t0.w;
            xv[4]=t1.x; xv[5]=t1.y; xv[6]=t1.z; xv[7]=t1.w;
            const float4* epp = (const float4*)(g_esum + (size_t)n * 8);
            float4 u0 = epp[0], u1 = epp[1];
            ev[0]=u0.x; ev[1]=u0.y; ev[2]=u0.z; ev[3]=u0.w;
            ev[4]=u1.x; ev[5]=u1.y; ev[6]=u1.z; ev[7]=u1.w;
        }

        float acc[16];
        #pragma unroll
        for (int k = 0; k < 16; k++) acc[k] = 0.0f;

        #pragma unroll
        for (int a = 0; a < 8; a++) {
            #pragma unroll
            for (int b = 0; b < 8; b++) {
                float p = xv[a] * ev[b];
                int base = a * 32 + b * 4;
                float4 q0 = w4[base], q1 = w4[base+1], q2 = w4[base+2], q3 = w4[base+3];
                acc[0]+=p*q0.x;  acc[1]+=p*q0.y;  acc[2]+=p*q0.z;  acc[3]+=p*q0.w;
                acc[4]+=p*q1.x;  acc[5]+=p*q1.y;  acc[6]+=p*q1.z;  acc[7]+=p*q1.w;
                acc[8]+=p*q2.x;  acc[9]+=p*q2.y;  acc[10]+=p*q2.z; acc[11]+=p*q2.w;
                acc[12]+=p*q3.x; acc[13]+=p*q3.y; acc[14]+=p*q3.z; acc[15]+=p*q3.w;
            }
        }

        const float sc2 = 0.125f;  // 1/sqrt(8*8)
        float4* op = (float4*)(x_out + (size_t)n * 16);
        op[0] = make_float4(acc[0]*sc2,  acc[1]*sc2,  acc[2]*sc2,  acc[3]*sc2);
        op[1] = make_float4(acc[4]*sc2,  acc[5]*sc2,  acc[6]*sc2,  acc[7]*sc2);
        op[2] = make_float4(acc[8]*sc2,  acc[9]*sc2,  acc[10]*sc2, acc[11]*sc2);
        op[3] = make_float4(acc[12]*sc2, acc[13]*sc2, acc[14]*sc2, acc[15]*sc2);
    }
}

extern "C" void kernel_launch(void* const* d_in, const int* in_sizes, int n_in,
                              void* d_out, int out_size)
{
    const float* x    = (const float*)d_in[0];
    const int*   ei   = (const int*)  d_in[1];
    const float* attr = (const float*)d_in[2];
    const float* emb  = (const float*)d_in[3];
    const float* w1   = (const float*)d_in[4];
    const float* w2   = (const float*)d_in[5];
    const float* wn   = (const float*)d_in[6];

    float* out      = (float*)d_out;
    float* x_out    = out;                    // [N, 16]
    float* edge_out = out + N_NODES * 16;     // [E, 8]

    static int nsm = 0;
    if (!nsm) {
        cudaDeviceGetAttribute(&nsm, cudaDevAttrMultiProcessorCount, 0);
        if (nsm <= 0) nsm = 148;
        cudaFuncSetAttribute(edge_kernel,
                             cudaFuncAttributeMaxDynamicSharedMemorySize,
                             SMEM_TOTAL);
    }

    edge_kernel<<<nsm, THREADS, SMEM_TOTAL>>>(x, ei, attr, emb, w1, w2, wn,
                                              edge_out, x_out);
}

// round 16
// speedup vs baseline: 1.2197x; 1.2197x over previous
#include <cuda_runtime.h>
#include <cuda_fp16.h>
#include <cstdint>

#define N_NODES 50000
#define N_EDGES 800000
#define TILE_M  256
#define NTILES  (N_EDGES / TILE_M)   // 3125
#define THREADS 256

// ---- smem layout (bytes) ----
#define OFF_BP   0                               // 64nt * 2kpair * 32lane * 16B = 64K
#define OFF_ZS   65536                           // 2 bufs * 256 rows * 80B (z[16] + at[4])
#define OFF_EM   (OFF_ZS + 2*256*80)             // 2 bufs * 256 rows * 80B (emb 64B + pad)
#define OFF_VJ   (OFF_EM + 2*256*80)             // 2 bufs * 256 int
#define SMEM_TOTAL (OFF_VJ + 2*256*4)            // 149504 B

__device__ float g_esum[N_NODES * 8];
__device__ unsigned int g_bar = 0;   // monotonic ticket counter (never reset; round-up target)

// pack two f32 -> f16x2 (first arg -> low half)
__device__ __forceinline__ uint32_t pack_f16x2(float lo, float hi) {
    uint32_t r;
    asm("cvt.rn.f16x2.f32 %0, %1, %2;" : "=r"(r) : "f"(hi), "f"(lo));
    return r;
}

__device__ __forceinline__ uint32_t smem_u32(const void* p) {
    uint32_t a;
    asm("{ .reg .u64 t; cvta.to.shared.u64 t, %1; cvt.u32.u64 %0, t; }"
        : "=r"(a) : "l"(p));
    return a;
}

__device__ __forceinline__ void cp16(uint32_t dst, const void* src) {
    asm volatile("cp.async.cg.shared.global [%0], [%1], 16;"
                 :: "r"(dst), "l"(src) : "memory");
}
#define CP_COMMIT() asm volatile("cp.async.commit_group;" ::: "memory")
#define CP_WAIT0()  asm volatile("cp.async.wait_group 0;" ::: "memory")

__device__ __forceinline__ void mma_f16(float d[4],
                                        uint32_t a0, uint32_t a1, uint32_t a2, uint32_t a3,
                                        uint32_t b0, uint32_t b1) {
    asm volatile(
        "mma.sync.aligned.m16n8k16.row.col.f32.f16.f16.f32 "
        "{%0,%1,%2,%3}, {%4,%5,%6,%7}, {%8,%9}, {%0,%1,%2,%3};"
        : "+f"(d[0]), "+f"(d[1]), "+f"(d[2]), "+f"(d[3])
        : "r"(a0), "r"(a1), "r"(a2), "r"(a3), "r"(b0), "r"(b1));
}

// C = 0 variant (no accumulator zeroing MOVs)
__device__ __forceinline__ void mma_f16_z(float d[4],
                                          uint32_t a0, uint32_t a1, uint32_t a2, uint32_t a3,
                                          uint32_t b0, uint32_t b1, float zz) {
    asm volatile(
        "mma.sync.aligned.m16n8k16.row.col.f32.f16.f16.f32 "
        "{%0,%1,%2,%3}, {%4,%5,%6,%7}, {%8,%9}, {%10,%10,%10,%10};"
        : "=f"(d[0]), "=f"(d[1]), "=f"(d[2]), "=f"(d[3])
        : "r"(a0), "r"(a1), "r"(a2), "r"(a3), "r"(b0), "r"(b1), "f"(zz));
}

__device__ __forceinline__ float fsilu(float s) {
    return __fdividef(s, 1.0f + __expf(-s));
}

__device__ __forceinline__ void red_addf(float* p, float v) {
    asm volatile("red.global.add.f32 [%0], %1;" :: "l"(p), "f"(v) : "memory");
}

__global__ __launch_bounds__(THREADS, 1)
void edge_kernel(const float* __restrict__ x,
                 const int*   __restrict__ ei,
                 const float* __restrict__ attr,
                 const float* __restrict__ emb,
                 const float* __restrict__ w1,
                 const float* __restrict__ w2,
                 float*       __restrict__ edge_out)
{
    extern __shared__ char smem[];
    const uint32_t sb = smem_u32(smem);
    const int tid  = threadIdx.x;
    const int lane = tid & 31;
    const int gID  = lane >> 2;
    const int tig  = lane & 3;
    const int wid  = tid >> 5;

    // ---- fused zero of g_esum (grid-stride slice per CTA) ----
    {
        float4* ez = (float4*)g_esum;
        const int tot = N_NODES * 2;          // float4 count
        for (int i = blockIdx.x * THREADS + tid; i < tot; i += gridDim.x * THREADS)
            ez[i] = make_float4(0.f, 0.f, 0.f, 0.f);
    }

    // ---- w1 B-fragments in registers, fp16 hi/lo split (persist whole kernel)
    uint32_t w1h[8][2], w1l[8][2];
    #pragma unroll
    for (int nt = 0; nt < 8; nt++) {
        const int c = nt * 8 + gID;
        #pragma unroll
        for (int jj = 0; jj < 2; jj++) {
            const int d0 = 2 * tig + jj * 8;
            float v0 = w1[d0 * 64 + c];
            float v1 = w1[(d0 + 1) * 64 + c];
            float h0 = __half2float(__float2half_rn(v0));
            float h1 = __half2float(__float2half_rn(v1));
            w1h[nt][jj] = pack_f16x2(h0, h1);
            w1l[nt][jj] = pack_f16x2(v0 - h0, v1 - h1);
        }
    }

    // ---- preload W2 as packed single-fp16 B fragments ----
    for (int ent = tid; ent < 4096; ent += THREADS) {
        int l  = ent & 31;
        int kp = (ent >> 5) & 1;
        int nt = ent >> 6;
        int n  = nt * 8 + (l >> 2);
        uint4 pk;
        #pragma unroll
        for (int half = 0; half < 2; half++) {
            int ks = kp * 2 + half;
            int k0 = ks * 16 + (l & 3) * 2;
            float v0 = w2[(k0    ) * 512 + n];
            float v1 = w2[(k0 + 1) * 512 + n];
            float v2 = w2[(k0 + 8) * 512 + n];
            float v3 = w2[(k0 + 9) * 512 + n];
            if (half == 0) { pk.x = pack_f16x2(v0, v1); pk.y = pack_f16x2(v2, v3); }
            else           { pk.z = pack_f16x2(v0, v1); pk.w = pack_f16x2(v2, v3); }
        }
        *(uint4*)(smem + OFF_BP + (size_t)ent * 16) = pk;
    }

    // ---- prologue: stage tile0 into buf 0 (direct) ----
    {
        const int e = blockIdx.x * TILE_M + tid;
        const int vi = ei[e];
        const int vj = ei[N_EDGES + e];
        float4* zr = (float4*)(smem + OFF_ZS + (size_t)tid * 80);
        const float4* xp = (const float4*)(x + (size_t)vi * 8);
        zr[0] = xp[0]; zr[1] = xp[1];
        const float4* xq = (const float4*)(x + (size_t)vj * 8);
        zr[2] = xq[0]; zr[3] = xq[1];
        zr[4] = ((const float4*)attr)[e];
        float4* er = (float4*)(smem + OFF_EM + (size_t)tid * 80);
        const float4* ep = (const float4*)(emb + (size_t)e * 16);
        er[0] = ep[0]; er[1] = ep[1]; er[2] = ep[2]; er[3] = ep[3];
        *(int*)(smem + OFF_VJ + (size_t)tid * 4) = vj;
    }
    // ---- prefetch tile1's indices into registers (2 regs only) ----
    int nvi = 0, nvj = 0;
    {
        const int t1 = blockIdx.x + gridDim.x;
        if (t1 < NTILES) {
            const int e = t1 * TILE_M + tid;
            nvi = ei[e];
            nvj = ei[N_EDGES + e];
        }
    }

    // ---- grid-wide spin barrier: all CTAs' zero slices visible before any RED ----
    // Ticket counter is monotonic across graph replays: round ticket up to the
    // next multiple of gridDim.x; all CTAs of this launch share that target.
    __threadfence();                               // release: zeros visible
    if (tid == 0) {
        const unsigned g = gridDim.x;
        unsigned t = atomicAdd(&g_bar, 1u) + 1u;
        unsigned target = ((t + g - 1u) / g) * g;
        while (atomicAdd(&g_bar, 0u) < target) { }
    }
    __syncthreads();                               // also covers smem staging above
    __threadfence();                               // acquire side

    int it = 0;
    for (int tile = blockIdx.x; tile < NTILES; tile += gridDim.x, it++) {
        const int buf  = it & 1;
        const int nbuf = buf ^ 1;
        const int ntile = tile + gridDim.x;
        const bool hn = (ntile < NTILES);

        // ---- issue async staging for tile+1 (no register residency) ----
        if (hn) {
            const int e1 = ntile * TILE_M + tid;
            const uint32_t zdst = sb + OFF_ZS + (uint32_t)(nbuf * 256 + tid) * 80;
            const float* xi = x + (size_t)nvi * 8;
            const float* xj = x + (size_t)nvj * 8;
            cp16(zdst,      xi);     cp16(zdst + 16, xi + 4);
            cp16(zdst + 32, xj);     cp16(zdst + 48, xj + 4);
            cp16(zdst + 64, attr + (size_t)e1 * 4);
            const uint32_t edst = sb + OFF_EM + (uint32_t)(nbuf * 256 + tid) * 80;
            const float* ep = emb + (size_t)e1 * 16;
            cp16(edst,      ep);     cp16(edst + 16, ep + 4);
            cp16(edst + 32, ep + 8); cp16(edst + 48, ep + 12);
            *(int*)(smem + OFF_VJ + (size_t)(nbuf * 256 + tid) * 4) = nvj;
            CP_COMMIT();
            // prefetch tile+2 indices
            const int nnt = ntile + gridDim.x;
            if (nnt < NTILES) {
                const int e2 = nnt * TILE_M + tid;
                nvi = ei[e2];
                nvj = ei[N_EDGES + e2];
            }
        }

        const int wbase = wid * 32;           // 8 warps x 32 edge-rows
        const float fz = 0.0f;
        #pragma unroll 1                      // keep contexts disjoint (R12 lesson)
        for (int mt = 0; mt < 2; mt++) {
            const int r0 = wbase + mt * 16 + gID;
            const int r8 = r0 + 8;
            const int e0 = tile * TILE_M + r0;
            const int e8 = tile * TILE_M + r8;

            // ---- emb A-fragments from staged smem, single fp16 ----
            uint32_t a16[4];
            {
                const char* er0 = smem + OFF_EM + (size_t)(buf * 256 + r0) * 80;
                const char* er8 = smem + OFF_EM + (size_t)(buf * 256 + r8) * 80;
                float2 v[4];
                v[0] = *(const float2*)(er0 + tig * 8);
                v[1] = *(const float2*)(er8 + tig * 8);
                v[2] = *(const float2*)(er0 + tig * 8 + 32);
                v[3] = *(const float2*)(er8 + tig * 8 + 32);
                #pragma unroll
                for (int q = 0; q < 4; q++)
                    a16[q] = pack_f16x2(v[q].x, v[q].y);
            }

            // ---- phase-1 MMA (2-pass: emb16 x (w1h + w1l)) -> silu -> A-frags
            uint32_t af[4][4];
            #pragma unroll
            for (int ks = 0; ks < 4; ks++) {
                #pragma unroll
                for (int j = 0; j < 2; j++) {
                    const int nt = 2 * ks + j;
                    float dd[4];
                    mma_f16_z(dd, a16[0], a16[1], a16[2], a16[3], w1h[nt][0], w1h[nt][1], fz);
                    mma_f16 (dd, a16[0], a16[1], a16[2], a16[3], w1l[nt][0], w1l[nt][1]);
                    float h0 = fsilu(dd[0] * 0.25f);
                    float h1 = fsilu(dd[1] * 0.25f);
                    float h2 = fsilu(dd[2] * 0.25f);
                    float h3 = fsilu(dd[3] * 0.25f);
                    af[ks][2 * j]     = pack_f16x2(h0, h1);   // (r0, k-cols)
                    af[ks][2 * j + 1] = pack_f16x2(h2, h3);   // (r8, k-cols)
                }
            }

            // ---- z / attr from staged smem (80B stride) ----
            float z0[16], z1[16], at0[4], at1[4];
            {
                const float4* q0 = (const float4*)(smem + OFF_ZS + (size_t)(buf * 256 + r0) * 80);
                const float4* q1 = (const float4*)(smem + OFF_ZS + (size_t)(buf * 256 + r8) * 80);
                #pragma unroll
                for (int q = 0; q < 4; q++) {
                    float4 a = q0[q]; z0[4*q]=a.x; z0[4*q+1]=a.y; z0[4*q+2]=a.z; z0[4*q+3]=a.w;
                    float4 b = q1[q]; z1[4*q]=b.x; z1[4*q+1]=b.y; z1[4*q+2]=b.z; z1[4*q+3]=b.w;
                }
                float4 a = q0[4]; at0[0]=a.x; at0[1]=a.y; at0[2]=a.z; at0[3]=a.w;
                float4 b = q1[4]; at1[0]=b.x; at1[1]=b.y; at1[2]=b.z; at1[3]=b.w;
            }

            float acc0 = 0.f, acc1 = 0.f, acc2 = 0.f, acc3 = 0.f;

            #pragma unroll
            for (int nt = 0; nt < 64; nt++) {      // FULL unroll: const z/at indices
                float d1[4];
                const uint4* bp = (const uint4*)(smem + OFF_BP + (size_t)nt * 1024) + lane;
                {
                    uint4 b01 = bp[0];        // ks0 (x,y), ks1 (z,w)
                    mma_f16_z(d1, af[0][0], af[0][1], af[0][2], af[0][3], b01.x, b01.y, fz);
                    mma_f16 (d1, af[1][0], af[1][1], af[1][2], af[1][3], b01.z, b01.w);
                }
                {
                    uint4 b23 = bp[32];       // ks2 (x,y), ks3 (z,w)
                    mma_f16 (d1, af[2][0], af[2][1], af[2][2], af[2][3], b23.x, b23.y);
                    mma_f16 (d1, af[3][0], af[3][1], af[3][2], af[3][3], b23.z, b23.w);
                }
                const float c0 = at0[nt >> 4] * z0[nt & 15];
                const float c1 = at1[nt >> 4] * z1[nt & 15];
                acc0 += c0 * d1[0];
                acc1 += c0 * d1[1];
                acc2 += c1 * d1[2];
                acc3 += c1 * d1[3];
            }

            const float sc = 1.0f / 64.0f;
            acc0 *= sc; acc1 *= sc; acc2 *= sc; acc3 *= sc;
            *(float2*)(edge_out + (size_t)e0 * 8 + 2 * tig) = make_float2(acc0, acc1);
            *(float2*)(edge_out + (size_t)e8 * 8 + 2 * tig) = make_float2(acc2, acc3);
            const int vj0 = *(const int*)(smem + OFF_VJ + (size_t)(buf * 256 + r0) * 4);
            const int vj1 = *(const int*)(smem + OFF_VJ + (size_t)(buf * 256 + r8) * 4);
            red_addf(g_esum + (size_t)vj0 * 8 + 2 * tig,     acc0);
            red_addf(g_esum + (size_t)vj0 * 8 + 2 * tig + 1, acc1);
            red_addf(g_esum + (size_t)vj1 * 8 + 2 * tig,     acc2);
            red_addf(g_esum + (size_t)vj1 * 8 + 2 * tig + 1, acc3);
        }

        CP_WAIT0();        // async staging for tile+1 has landed
        __syncthreads();
    }
}

__global__ __launch_bounds__(256)
void node_kernel(const float* __restrict__ x,
                 const float* __restrict__ w_node,
                 float*       __restrict__ x_out)
{
    __shared__ float swn[1024];   // [a][b][k]
    for (int idx = threadIdx.x; idx < 1024; idx += blockDim.x)
        swn[idx] = w_node[idx];
    __syncthreads();

    int n = blockIdx.x * blockDim.x + threadIdx.x;
    if (n >= N_NODES) return;

    float xv[8], ev[8];
    {
        const float4* xp = (const float4*)(x + (size_t)n * 8);
        float4 t0 = xp[0], t1 = xp[1];
        xv[0]=t0.x; xv[1]=t0.y; xv[2]=t0.z; xv[3]=t0.w;
        xv[4]=t1.x; xv[5]=t1.y; xv[6]=t1.z; xv[7]=t1.w;
        const float4* epp = (const float4*)(g_esum + (size_t)n * 8);
        float4 u0 = epp[0], u1 = epp[1];
        ev[0]=u0.x; ev[1]=u0.y; ev[2]=u0.z; ev[3]=u0.w;
        ev[4]=u1.x; ev[5]=u1.y; ev[6]=u1.z; ev[7]=u1.w;
    }

    float acc[16];
    #pragma unroll
    for (int k = 0; k < 16; k++) acc[k] = 0.0f;

    const float4* w4 = (const float4*)swn;
    #pragma unroll
    for (int a = 0; a < 8; a++) {
        #pragma unroll
        for (int b = 0; b < 8; b++) {
            float p = xv[a] * ev[b];
            int base = a * 32 + b * 4;
            float4 q0 = w4[base], q1 = w4[base+1], q2 = w4[base+2], q3 = w4[base+3];
            acc[0]+=p*q0.x;  acc[1]+=p*q0.y;  acc[2]+=p*q0.z;  acc[3]+=p*q0.w;
            acc[4]+=p*q1.x;  acc[5]+=p*q1.y;  acc[6]+=p*q1.z;  acc[7]+=p*q1.w;
            acc[8]+=p*q2.x;  acc[9]+=p*q2.y;  acc[10]+=p*q2.z; acc[11]+=p*q2.w;
            acc[12]+=p*q3.x; acc[13]+=p*q3.y; acc[14]+=p*q3.z; acc[15]+=p*q3.w;
        }
    }

    const float sc = 0.125f;
    float4* op = (float4*)(x_out + (size_t)n * 16);
    op[0] = make_float4(acc[0]*sc,  acc[1]*sc,  acc[2]*sc,  acc[3]*sc);
    op[1] = make_float4(acc[4]*sc,  acc[5]*sc,  acc[6]*sc,  acc[7]*sc);
    op[2] = make_float4(acc[8]*sc,  acc[9]*sc,  acc[10]*sc, acc[11]*sc);
    op[3] = make_float4(acc[12]*sc, acc[13]*sc, acc[14]*sc, acc[15]*sc);
}

extern "C" void kernel_launch(void* const* d_in, const int* in_sizes, int n_in,
                              void* d_out, int out_size)
{
    const float* x    = (const float*)d_in[0];
    const int*   ei   = (const int*)  d_in[1];
    const float* attr = (const float*)d_in[2];
    const float* emb  = (const float*)d_in[3];
    const float* w1   = (const float*)d_in[4];
    const float* w2   = (const float*)d_in[5];
    const float* wn   = (const float*)d_in[6];

    float* out      = (float*)d_out;
    float* x_out    = out;                    // [N, 16]
    float* edge_out = out + N_NODES * 16;     // [E, 8]

    static int nsm = 0;
    if (!nsm) {
        cudaDeviceGetAttribute(&nsm, cudaDevAttrMultiProcessorCount, 0);
        if (nsm <= 0) nsm = 148;
        cudaFuncSetAttribute(edge_kernel,
                             cudaFuncAttributeMaxDynamicSharedMemorySize,
                             SMEM_TOTAL);
    }

    edge_kernel<<<nsm, THREADS, SMEM_TOTAL>>>(x, ei, attr, emb, w1, w2, edge_out);
    node_kernel<<<(N_NODES + 255) / 256, 256>>>(x, wn, x_out);
}